// round 14
// baseline (speedup 1.0000x reference)
#include <cuda_runtime.h>
#include <cstdint>
#include <cfloat>

#define B_  32
#define K_  17
#define H_  192
#define W_  192
#define C_  19
#define P_  20
#define S_  10
#define HW_ (H_*W_)
#define NCH (B_*K_)

#define PEAK_THRESH      0.1f
#define PAF_SCORE_THRESH 0.05f
#define PAF_COUNT_THRESH 0.8f

#define CAND_CAP 5120
#define SURV_CAP 128
#define NBINS    256
#define CTA_BUF  2048     // 64 rows * 192 px * ~0.115 ~ 1414 expected

#define QX   48           // quads per row (192/4)
#define TY   8            // thread rows per CTA
#define RPT  8            // pixel rows per thread
#define CTAROWS (TY*RPT)  // 64 rows per CTA
#define NTS  (QX*TY)      // 384 threads

__constant__ int SKEL_A[C_] = {15,13,16,14,11, 5, 6, 5, 5, 6, 7, 8, 1, 0, 0, 1, 2, 3, 4};
__constant__ int SKEL_B[C_] = {13,11,14,12,12,11,12, 6, 7, 8, 9,10, 2, 1, 2, 3, 4, 5, 6};

// global scratch (zero-initialized at load; select restores zeros each run)
__device__ unsigned long long g_keys[NCH][CAND_CAP];
__device__ int g_count[NCH];
__device__ int g_hist[NCH][NBINS];

__device__ __forceinline__ float fmax3(float a, float b, float c) {
    return fmaxf(a, fmaxf(b, c));
}

// ---------------------------------------------------------------------------
// Kernel 1a: streaming peak scan (R10 measured-best, byte-identical).
// ---------------------------------------------------------------------------
__global__ __launch_bounds__(NTS)
void peaks_scan(const float* __restrict__ heat)
{
    const int bk = blockIdx.y;
    const float* __restrict__ h = heat + (size_t)bk * HW_;

    const int qx  = threadIdx.x;                        // 0..47
    const int y0  = blockIdx.x * CTAROWS + threadIdx.y * RPT;
    const int tid = threadIdx.y * QX + threadIdx.x;
    const int lane = tid & 31;
    const int x0  = qx * 4;

    __shared__ unsigned long long s_buf[CTA_BUF];
    __shared__ int s_hist[NBINS];
    __shared__ int s_cnt;
    __shared__ int s_gbase;

    for (int i = tid; i < NBINS; i += NTS) s_hist[i] = 0;
    if (tid == 0) s_cnt = 0;
    __syncthreads();

    const bool is_l = (lane == 0)  && (qx > 0);
    const bool is_r = (lane == 31) && (qx < QX - 1);
    const float4 NEG4 = make_float4(-FLT_MAX, -FLT_MAX, -FLT_MAX, -FLT_MAX);
    const float THR = __uint_as_float(0x3DCCCCCEu);   // nextafter(0.1f, +inf)

    float4 a, b;
    float el_a = -FLT_MAX, el_b = -FLT_MAX;
    float er_a = -FLT_MAX, er_b = -FLT_MAX;
    {
        const float* rw = h + (size_t)y0 * W_;
        b = __ldg((const float4*)rw + qx);
        if (is_l) el_b = __ldg(rw + x0 - 1);
        if (is_r) er_b = __ldg(rw + x0 + 4);
        if (y0 > 0) {
            a = __ldg((const float4*)(rw - W_) + qx);
            if (is_l) el_a = __ldg(rw - W_ + x0 - 1);
            if (is_r) er_a = __ldg(rw - W_ + x0 + 4);
        } else {
            a = NEG4;
        }
    }

    #pragma unroll
    for (int r = 0; r < RPT; r++) {
        const int y = y0 + r;
        float4 c;
        float el_c = -FLT_MAX, er_c = -FLT_MAX;
        if (y + 1 < H_) {
            const float* rd = h + (size_t)(y + 1) * W_;
            c = __ldg((const float4*)rd + qx);
            if (is_l) el_c = __ldg(rd + x0 - 1);
            if (is_r) er_c = __ldg(rd + x0 + 4);
        } else {
            c = NEG4;
        }

        float v0 = fmax3(a.x, b.x, c.x);
        float v1 = fmax3(a.y, b.y, c.y);
        float v2 = fmax3(a.z, b.z, c.z);
        float v3 = fmax3(a.w, b.w, c.w);

        float vl = __shfl_up_sync(0xffffffffu, v3, 1);
        if (lane == 0)   vl = fmax3(el_a, el_b, el_c);
        if (qx == 0)     vl = -FLT_MAX;
        float vr = __shfl_down_sync(0xffffffffu, v0, 1);
        if (lane == 31)  vr = fmax3(er_a, er_b, er_c);
        if (qx == QX-1)  vr = -FLT_MAX;

        float m01 = fmaxf(v0, v1);
        float m23 = fmaxf(v2, v3);
        float w0 = fmaxf(fmaxf(vl,  m01), THR);
        float w1 = fmaxf(fmaxf(m01, v2),  THR);
        float w2 = fmaxf(fmaxf(v1,  m23), THR);
        float w3 = fmaxf(fmaxf(m23, vr),  THR);

        const bool p0 = (b.x >= w0);
        const bool p1 = (b.y >= w1);
        const bool p2 = (b.z >= w2);
        const bool p3 = (b.w >= w3);

        unsigned m0 = __ballot_sync(0xffffffffu, p0);
        unsigned m1 = __ballot_sync(0xffffffffu, p1);
        unsigned m2 = __ballot_sync(0xffffffffu, p2);
        unsigned m3 = __ballot_sync(0xffffffffu, p3);
        int n0 = __popc(m0), n1 = __popc(m1), n2 = __popc(m2);
        int total = n0 + n1 + n2 + __popc(m3);

        if (total) {   // warp-uniform
            int base = 0;
            if (lane == 0) base = atomicAdd(&s_cnt, total);
            base = __shfl_sync(0xffffffffu, base, 0);
            const unsigned lt = (1u << lane) - 1u;
            const int prow = y * W_ + x0;
            #define STORE_PK(v, pos, pix)                                           \
                do { int _p = (pos);                                                \
                     if (_p < CTA_BUF) {                                            \
                         s_buf[_p] = ((unsigned long long)__float_as_uint(v) << 32) \
                                   | (unsigned)(0xFFFFFFFFu - (unsigned)(pix));     \
                         atomicAdd(&s_hist[min(NBINS-1, (int)((v)*(float)NBINS))], 1);\
                     } } while (0)
            if (p0) STORE_PK(b.x, base + __popc(m0 & lt),                prow);
            if (p1) STORE_PK(b.y, base + n0 + __popc(m1 & lt),           prow + 1);
            if (p2) STORE_PK(b.z, base + n0 + n1 + __popc(m2 & lt),      prow + 2);
            if (p3) STORE_PK(b.w, base + n0 + n1 + n2 + __popc(m3 & lt), prow + 3);
            #undef STORE_PK
        }

        a = b; b = c;
        el_a = el_b; el_b = el_c;
        er_a = er_b; er_b = er_c;
    }
    __syncthreads();

    const int n = min(s_cnt, CTA_BUF);
    if (tid == 0 && n > 0) s_gbase = atomicAdd(&g_count[bk], n);
    __syncthreads();

    if (n > 0) {
        const int gbase = s_gbase;
        for (int i = tid; i < n; i += NTS) {
            int pos = gbase + i;
            if (pos < CAND_CAP) g_keys[bk][pos] = s_buf[i];
        }
    }
    for (int i = tid; i < NBINS; i += NTS) {
        int hv = s_hist[i];
        if (hv) atomicAdd(&g_hist[bk][i], hv);   // fire-and-forget RED
    }
}

// ---------------------------------------------------------------------------
// Kernel 1b: WARP-PER-CHANNEL top-20 selection. No block barriers.
// ---------------------------------------------------------------------------
#define SEL_WARPS 8
#define SEL_NT    (SEL_WARPS * 32)
__global__ __launch_bounds__(SEL_NT)
void peaks_select(const float* __restrict__ heat, float* __restrict__ out_peaks)
{
    const int w    = threadIdx.x >> 5;
    const int lane = threadIdx.x & 31;
    const int bk   = blockIdx.x * SEL_WARPS + w;
    const float* __restrict__ h = heat + (size_t)bk * HW_;

    __shared__ unsigned long long surv[SEL_WARPS][SURV_CAP];   // 8 KB
    __shared__ int s_nsurv[SEL_WARPS];

    if (lane == 0) s_nsurv[w] = 0;

    // stage nc and reset counter (lane 0 reads, broadcast via shfl)
    int nc = 0;
    if (lane == 0) { nc = min(g_count[bk], CAND_CAP); g_count[bk] = 0; }
    nc = __shfl_sync(0xffffffffu, nc, 0);

    // stage histogram (8 descending bins per lane) + reset for next run
    int lh[8];
    int lsum = 0;
    #pragma unroll
    for (int k = 0; k < 8; k++) {
        int bin = NBINS - 1 - (lane * 8 + k);
        lh[k] = g_hist[bk][bin];
        lsum += lh[k];
    }
    #pragma unroll
    for (int k = 0; k < 8; k++)
        g_hist[bk][lane * 8 + k] = 0;

    // in-warp suffix threshold search
    int excl = lsum;
    #pragma unroll
    for (int d = 1; d < 32; d <<= 1) {
        int nn = __shfl_up_sync(0xffffffffu, excl, d);
        if (lane >= d) excl += nn;
    }
    int tot = __shfl_sync(0xffffffffu, excl, 31);
    excl -= lsum;

    const int need = min(P_, nc);
    int tbin = 0;
    if (need > 0 && tot >= need) {
        bool crossing = (excl < need) && (excl + lsum >= need);
        unsigned cm = __ballot_sync(0xffffffffu, crossing);
        int src = __ffs(cm) - 1;
        if (lane == src) {
            int cum = excl;
            #pragma unroll
            for (int k = 0; k < 8; k++) {
                cum += lh[k];
                if (cum >= need) { tbin = NBINS - 1 - (lane * 8 + k); break; }
            }
        }
        tbin = __shfl_sync(0xffffffffu, tbin, src);
    }

    // single filter pass over the channel's keys
    const unsigned long long kthr = (unsigned long long)
        ((unsigned)tbin) << 56;  // key >= tbin<<56  <=>  score-bin >= tbin (approx lower bound)
    (void)kthr;
    for (int i = lane; i < nc; i += 32) {
        unsigned long long k = g_keys[bk][i];
        float sc = __uint_as_float((unsigned)(k >> 32));
        int bin = min(NBINS - 1, (int)(sc * (float)NBINS));
        if (bin >= tbin) {
            int slot = atomicAdd(&s_nsurv[w], 1);
            if (slot < SURV_CAP) surv[w][slot] = k;
        }
    }
    __syncwarp();

    // 20 argmax rounds (top_k semantics: score desc, index asc)
    unsigned long long sel[1];
    unsigned long long mykey = 0ull;   // key selected for this lane's round (lane r)
    {
        unsigned long long* list;
        int len;
        int ns = s_nsurv[w];
        if (ns <= SURV_CAP) { list = surv[w]; len = ns; }
        else                { list = &g_keys[bk][0]; len = nc; }   // rare fallback

        for (int r = 0; r < P_; r++) {
            unsigned long long bkey = 0ull;
            int bidx = -1;
            for (int i = lane; i < len; i += 32) {
                unsigned long long k = list[i];
                if (k > bkey) { bkey = k; bidx = i; }
            }
            #pragma unroll
            for (int o = 16; o > 0; o >>= 1) {
                unsigned long long ok = __shfl_down_sync(0xffffffffu, bkey, o);
                int oi = __shfl_down_sync(0xffffffffu, bidx, o);
                if (ok > bkey) { bkey = ok; bidx = oi; }
            }
            bkey = __shfl_sync(0xffffffffu, bkey, 0);
            bidx = __shfl_sync(0xffffffffu, bidx, 0);
            if (lane == r) mykey = bkey;
            if (lane == 0 && bidx >= 0) list[bidx] = 0ull;
            __syncwarp();
        }
    }
    sel[0] = mykey;

    // subpixel refine + write (lanes 0..19 hold round-r keys)
    if (lane < P_) {
        unsigned long long k = sel[0];
        float px = 0.0f, py = 0.0f, so = 0.0f;
        if (k != 0ull) {
            float sc = __uint_as_float((unsigned)(k >> 32));
            int p = (int)(0xFFFFFFFFu - (unsigned)(k & 0xFFFFFFFFull));
            int y = p / W_;
            int x = p - y * W_;
            float ddx = 0.0f, ddy = 0.0f;
            if (x > 0 && x < W_-1 && y > 0 && y < H_-1) {
                float c  = h[p];
                float rr = h[p + 1],  ll = h[p - 1];
                float dd = h[p + W_], uu = h[p - W_];
                float dx  = 0.5f * (rr - ll);
                float dxx = (rr + ll) - 2.0f * c;
                if (dxx != 0.0f) dx = dx / (-dxx);
                float dy  = 0.5f * (dd - uu);
                float dyy = (dd + uu) - 2.0f * c;
                if (dyy != 0.0f) dy = dy / (-dyy);
                ddx = dx; ddy = dy;
            }
            px = (float)x + ddx;
            py = (float)y + ddy;
            so = sc;
        }
        float* o = out_peaks + ((size_t)bk * P_ + lane) * 3;
        o[0] = px; o[1] = py; o[2] = so;
    }
}

// ---------------------------------------------------------------------------
// Kernel 2: flat one-thread-per-cell PAF line-integral scoring (R10 best).
// ---------------------------------------------------------------------------
#define NT2 256
#define NCELLS (B_*C_*P_*P_)
__global__ __launch_bounds__(NT2)
void conn_kernel(const float* __restrict__ paf,
                 const float* __restrict__ peaks,
                 float* __restrict__ conn)
{
    const int gid = blockIdx.x * NT2 + threadIdx.x;
    if (gid >= NCELLS) return;

    int j = gid % P_;
    int t = gid / P_;
    int i = t % P_;  t /= P_;
    int c = t % C_;
    int b = t / C_;

    const float* pkA = peaks + (((size_t)b * K_ + SKEL_A[c]) * P_ + i) * 3;
    const float* pkB = peaks + (((size_t)b * K_ + SKEL_B[c]) * P_ + j) * 3;
    float axi = __ldg(pkA + 0), ayi = __ldg(pkA + 1), sa = __ldg(pkA + 2);
    float bxj = __ldg(pkB + 0), byj = __ldg(pkB + 1), sb = __ldg(pkB + 2);

    const float* __restrict__ pafx = paf + ((size_t)b * (2*C_) + 2*c) * HW_;
    const float* __restrict__ pafy = pafx + HW_;

    const float delta = 1.0f / 9.0f;

    float dxl = bxj - axi;
    float dyl = byj - ayi;
    float norm = sqrtf(dxl*dxl + dyl*dyl) + 1e-8f;
    float vx = dxl / norm, vy = dyl / norm;

    int   idx[S_];
    bool  inb[S_];
    #pragma unroll
    for (int s = 0; s < S_; s++) {
        float t2 = (s == S_-1) ? 1.0f : (float)s * delta;
        float xs = axi + dxl * t2;
        float ys = ayi + dyl * t2;
        int xi = __float2int_rz(xs);
        int yi = __float2int_rz(ys);
        inb[s] = (xi >= 0) & (xi < W_) & (yi >= 0) & (yi < H_);
        int xc = min(max(xi, 0), W_ - 1);
        int yc = min(max(yi, 0), H_ - 1);
        idx[s] = yc * W_ + xc;
    }

    float pxv[S_], pyv[S_];
    #pragma unroll
    for (int s = 0; s < S_; s++) pxv[s] = __ldg(pafx + idx[s]);
    #pragma unroll
    for (int s = 0; s < S_; s++) pyv[s] = __ldg(pafy + idx[s]);

    float cnt = 0.0f, sum = 0.0f, cntp = 0.0f;
    #pragma unroll
    for (int s = 0; s < S_; s++) {
        float vs = pxv[s] * vx + pyv[s] * vy;
        if (inb[s]) {
            cnt += 1.0f;
            sum += vs;
            if (vs > PAF_SCORE_THRESH) cntp += 1.0f;
        }
    }

    float denom = fmaxf(cnt, 1.0f);
    float mean  = sum / denom;
    float ratio = cntp / denom;
    bool ok = (cnt > 0.0f) && (mean > 0.0f) && (ratio > PAF_COUNT_THRESH)
              && (sa > PEAK_THRESH) && (sb > PEAK_THRESH);
    conn[gid] = ok ? (mean + 0.5f * (sa + sb)) : 0.0f;
}

// ---------------------------------------------------------------------------
extern "C" void kernel_launch(void* const* d_in, const int* in_sizes, int n_in,
                              void* d_out, int out_size)
{
    const float* heat = (const float*)d_in[0];
    const float* paf  = (const float*)d_in[1];
    if (n_in >= 2 && in_sizes[0] == B_ * 2 * C_ * HW_ && in_sizes[1] == B_ * K_ * HW_) {
        heat = (const float*)d_in[1];
        paf  = (const float*)d_in[0];
    }

    float* out_peaks = (float*)d_out;                      // B*K*P*3
    float* out_conn  = out_peaks + (size_t)B_ * K_ * P_ * 3;

    dim3 g1(H_ / CTAROWS, NCH);
    dim3 b1(QX, TY);
    peaks_scan<<<g1, b1>>>(heat);

    peaks_select<<<NCH / SEL_WARPS, SEL_NT>>>(heat, out_peaks);

    conn_kernel<<<(NCELLS + NT2 - 1) / NT2, NT2>>>(paf, out_peaks, out_conn);
}

// round 15
// speedup vs baseline: 2.9644x; 2.9644x over previous
#include <cuda_runtime.h>
#include <cstdint>
#include <cfloat>

#define B_  32
#define K_  17
#define H_  192
#define W_  192
#define C_  19
#define P_  20
#define S_  10
#define HW_ (H_*W_)
#define NCH (B_*K_)

#define PEAK_THRESH      0.1f
#define PAF_SCORE_THRESH 0.05f
#define PAF_COUNT_THRESH 0.8f

#define CAND_CAP 5120
#define SURV_CAP 512
#define NBINS    256
#define CTA_BUF  2048

#define QX   48
#define TY   8
#define RPT  8
#define CTAROWS (TY*RPT)
#define NTS  (QX*TY)

__constant__ int SKEL_A[C_] = {15,13,16,14,11, 5, 6, 5, 5, 6, 7, 8, 1, 0, 0, 1, 2, 3, 4};
__constant__ int SKEL_B[C_] = {13,11,14,12,12,11,12, 6, 7, 8, 9,10, 2, 1, 2, 3, 4, 5, 6};

__device__ unsigned long long g_keys[NCH][CAND_CAP];
__device__ int g_count[NCH];
__device__ int g_hist[NCH][NBINS];

__device__ __forceinline__ float fmax3(float a, float b, float c) {
    return fmaxf(a, fmaxf(b, c));
}

// ---------------------------------------------------------------------------
// Kernel 1a: streaming peak scan (R10 measured-best, byte-identical).
// ---------------------------------------------------------------------------
__global__ __launch_bounds__(NTS)
void peaks_scan(const float* __restrict__ heat)
{
    const int bk = blockIdx.y;
    const float* __restrict__ h = heat + (size_t)bk * HW_;

    const int qx  = threadIdx.x;
    const int y0  = blockIdx.x * CTAROWS + threadIdx.y * RPT;
    const int tid = threadIdx.y * QX + threadIdx.x;
    const int lane = tid & 31;
    const int x0  = qx * 4;

    __shared__ unsigned long long s_buf[CTA_BUF];
    __shared__ int s_hist[NBINS];
    __shared__ int s_cnt;
    __shared__ int s_gbase;

    for (int i = tid; i < NBINS; i += NTS) s_hist[i] = 0;
    if (tid == 0) s_cnt = 0;
    __syncthreads();

    const bool is_l = (lane == 0)  && (qx > 0);
    const bool is_r = (lane == 31) && (qx < QX - 1);
    const float4 NEG4 = make_float4(-FLT_MAX, -FLT_MAX, -FLT_MAX, -FLT_MAX);
    const float THR = __uint_as_float(0x3DCCCCCEu);   // nextafter(0.1f, +inf)

    float4 a, b;
    float el_a = -FLT_MAX, el_b = -FLT_MAX;
    float er_a = -FLT_MAX, er_b = -FLT_MAX;
    {
        const float* rw = h + (size_t)y0 * W_;
        b = __ldg((const float4*)rw + qx);
        if (is_l) el_b = __ldg(rw + x0 - 1);
        if (is_r) er_b = __ldg(rw + x0 + 4);
        if (y0 > 0) {
            a = __ldg((const float4*)(rw - W_) + qx);
            if (is_l) el_a = __ldg(rw - W_ + x0 - 1);
            if (is_r) er_a = __ldg(rw - W_ + x0 + 4);
        } else {
            a = NEG4;
        }
    }

    #pragma unroll
    for (int r = 0; r < RPT; r++) {
        const int y = y0 + r;
        float4 c;
        float el_c = -FLT_MAX, er_c = -FLT_MAX;
        if (y + 1 < H_) {
            const float* rd = h + (size_t)(y + 1) * W_;
            c = __ldg((const float4*)rd + qx);
            if (is_l) el_c = __ldg(rd + x0 - 1);
            if (is_r) er_c = __ldg(rd + x0 + 4);
        } else {
            c = NEG4;
        }

        float v0 = fmax3(a.x, b.x, c.x);
        float v1 = fmax3(a.y, b.y, c.y);
        float v2 = fmax3(a.z, b.z, c.z);
        float v3 = fmax3(a.w, b.w, c.w);

        float vl = __shfl_up_sync(0xffffffffu, v3, 1);
        if (lane == 0)   vl = fmax3(el_a, el_b, el_c);
        if (qx == 0)     vl = -FLT_MAX;
        float vr = __shfl_down_sync(0xffffffffu, v0, 1);
        if (lane == 31)  vr = fmax3(er_a, er_b, er_c);
        if (qx == QX-1)  vr = -FLT_MAX;

        float m01 = fmaxf(v0, v1);
        float m23 = fmaxf(v2, v3);
        float w0 = fmaxf(fmaxf(vl,  m01), THR);
        float w1 = fmaxf(fmaxf(m01, v2),  THR);
        float w2 = fmaxf(fmaxf(v1,  m23), THR);
        float w3 = fmaxf(fmaxf(m23, vr),  THR);

        const bool p0 = (b.x >= w0);
        const bool p1 = (b.y >= w1);
        const bool p2 = (b.z >= w2);
        const bool p3 = (b.w >= w3);

        unsigned m0 = __ballot_sync(0xffffffffu, p0);
        unsigned m1 = __ballot_sync(0xffffffffu, p1);
        unsigned m2 = __ballot_sync(0xffffffffu, p2);
        unsigned m3 = __ballot_sync(0xffffffffu, p3);
        int n0 = __popc(m0), n1 = __popc(m1), n2 = __popc(m2);
        int total = n0 + n1 + n2 + __popc(m3);

        if (total) {
            int base = 0;
            if (lane == 0) base = atomicAdd(&s_cnt, total);
            base = __shfl_sync(0xffffffffu, base, 0);
            const unsigned lt = (1u << lane) - 1u;
            const int prow = y * W_ + x0;
            #define STORE_PK(v, pos, pix)                                           \
                do { int _p = (pos);                                                \
                     if (_p < CTA_BUF) {                                            \
                         s_buf[_p] = ((unsigned long long)__float_as_uint(v) << 32) \
                                   | (unsigned)(0xFFFFFFFFu - (unsigned)(pix));     \
                         atomicAdd(&s_hist[min(NBINS-1, (int)((v)*(float)NBINS))], 1);\
                     } } while (0)
            if (p0) STORE_PK(b.x, base + __popc(m0 & lt),                prow);
            if (p1) STORE_PK(b.y, base + n0 + __popc(m1 & lt),           prow + 1);
            if (p2) STORE_PK(b.z, base + n0 + n1 + __popc(m2 & lt),      prow + 2);
            if (p3) STORE_PK(b.w, base + n0 + n1 + n2 + __popc(m3 & lt), prow + 3);
            #undef STORE_PK
        }

        a = b; b = c;
        el_a = el_b; el_b = el_c;
        er_a = er_b; er_b = er_c;
    }
    __syncthreads();

    const int n = min(s_cnt, CTA_BUF);
    if (tid == 0 && n > 0) s_gbase = atomicAdd(&g_count[bk], n);
    __syncthreads();

    if (n > 0) {
        const int gbase = s_gbase;
        for (int i = tid; i < n; i += NTS) {
            int pos = gbase + i;
            if (pos < CAND_CAP) g_keys[bk][pos] = s_buf[i];
        }
    }
    for (int i = tid; i < NBINS; i += NTS) {
        int hv = s_hist[i];
        if (hv) atomicAdd(&g_hist[bk][i], hv);
    }
}

// ---------------------------------------------------------------------------
// Kernel 1b: per-channel top-20 selection (R10 block form) + PDL entry sync.
// ---------------------------------------------------------------------------
#define NT1 256
__global__ __launch_bounds__(NT1)
void peaks_select(const float* __restrict__ heat, float* __restrict__ out_peaks)
{
    cudaGridDependencySynchronize();   // PDL: wait for scan grid + mem flush

    const int bk = blockIdx.x;
    const float* __restrict__ h = heat + (size_t)bk * HW_;

    __shared__ unsigned long long surv[SURV_CAP];
    __shared__ int   s_hist[NBINS];
    __shared__ int   s_nsurv, s_tbin;
    __shared__ unsigned long long sel_key[P_];

    const int tid  = threadIdx.x;
    const int lane = tid & 31;
    const int wid  = tid >> 5;

    const int nc = min(g_count[bk], CAND_CAP);

    s_hist[tid] = g_hist[bk][tid];
    if (tid == 0) s_nsurv = 0;
    __syncthreads();

    if (wid == 0) {
        const int need = min(P_, nc);
        int lsum = 0;
        int lh[8];
        #pragma unroll
        for (int k = 0; k < 8; k++) {
            lh[k] = s_hist[NBINS - 1 - (lane * 8 + k)];
            lsum += lh[k];
        }
        int excl = lsum;
        #pragma unroll
        for (int d = 1; d < 32; d <<= 1) {
            int nn = __shfl_up_sync(0xffffffffu, excl, d);
            if (lane >= d) excl += nn;
        }
        int tot = __shfl_sync(0xffffffffu, excl, 31);
        excl -= lsum;

        int tb = 0;
        if (need > 0 && tot >= need) {
            bool crossing = (excl < need) && (excl + lsum >= need);
            unsigned cm = __ballot_sync(0xffffffffu, crossing);
            int src = __ffs(cm) - 1;
            if (lane == src) {
                int cum = excl;
                #pragma unroll
                for (int k = 0; k < 8; k++) {
                    cum += lh[k];
                    if (cum >= need) { tb = NBINS - 1 - (lane * 8 + k); break; }
                }
            }
            tb = __shfl_sync(0xffffffffu, tb, src);
        }
        if (lane == 0) s_tbin = tb;
    }
    __syncthreads();
    const int tbin = s_tbin;

    for (int i = tid; i < nc; i += NT1) {
        unsigned long long k = g_keys[bk][i];
        float sc = __uint_as_float((unsigned)(k >> 32));
        int bin = min(NBINS - 1, (int)(sc * (float)NBINS));
        if (bin >= tbin) {
            int slot = atomicAdd(&s_nsurv, 1);
            if (slot < SURV_CAP) surv[slot] = k;
        }
    }
    __syncthreads();

    if (wid == 0) {
        unsigned long long* list;
        int len;
        if (s_nsurv <= SURV_CAP) { list = surv; len = s_nsurv; }
        else                     { list = &g_keys[bk][0]; len = nc; }

        for (int r = 0; r < P_; r++) {
            unsigned long long bkey = 0ull;
            int bidx = -1;
            for (int i = lane; i < len; i += 32) {
                unsigned long long k = list[i];
                if (k > bkey) { bkey = k; bidx = i; }
            }
            #pragma unroll
            for (int o = 16; o > 0; o >>= 1) {
                unsigned long long ok = __shfl_down_sync(0xffffffffu, bkey, o);
                int oi = __shfl_down_sync(0xffffffffu, bidx, o);
                if (ok > bkey) { bkey = ok; bidx = oi; }
            }
            if (lane == 0) {
                sel_key[r] = bkey;
                if (bidx >= 0) list[bidx] = 0ull;
            }
            __syncwarp();
        }
    }
    __syncthreads();

    if (tid < P_) {
        unsigned long long k = sel_key[tid];
        float px = 0.0f, py = 0.0f, so = 0.0f;
        if (k != 0ull) {
            float sc = __uint_as_float((unsigned)(k >> 32));
            int p = (int)(0xFFFFFFFFu - (unsigned)(k & 0xFFFFFFFFull));
            int y = p / W_;
            int x = p - y * W_;
            float ddx = 0.0f, ddy = 0.0f;
            if (x > 0 && x < W_-1 && y > 0 && y < H_-1) {
                float c  = h[p];
                float rr = h[p + 1],  ll = h[p - 1];
                float dd = h[p + W_], uu = h[p - W_];
                float dx  = 0.5f * (rr - ll);
                float dxx = (rr + ll) - 2.0f * c;
                if (dxx != 0.0f) dx = dx / (-dxx);
                float dy  = 0.5f * (dd - uu);
                float dyy = (dd + uu) - 2.0f * c;
                if (dyy != 0.0f) dy = dy / (-dyy);
                ddx = dx; ddy = dy;
            }
            px = (float)x + ddx;
            py = (float)y + ddy;
            so = sc;
        }
        float* o = out_peaks + ((size_t)bk * P_ + tid) * 3;
        o[0] = px; o[1] = py; o[2] = so;
    }

    if (tid == 0) g_count[bk] = 0;
    g_hist[bk][tid] = 0;
}

// ---------------------------------------------------------------------------
// Kernel 2: flat one-thread-per-cell PAF line-integral scoring + PDL sync.
// ---------------------------------------------------------------------------
#define NT2 256
#define NCELLS (B_*C_*P_*P_)
__global__ __launch_bounds__(NT2)
void conn_kernel(const float* __restrict__ paf,
                 const float* __restrict__ peaks,
                 float* __restrict__ conn)
{
    const int gid = blockIdx.x * NT2 + threadIdx.x;

    // setup that does NOT depend on select's output
    int j = gid % P_;
    int t = gid / P_;
    int i = t % P_;  t /= P_;
    int c = t % C_;
    int b = t / C_;

    const float* __restrict__ pafx = paf + ((size_t)b * (2*C_) + 2*c) * HW_;
    const float* __restrict__ pafy = pafx + HW_;
    const float* pkA = peaks + (((size_t)b * K_ + SKEL_A[c]) * P_ + i) * 3;
    const float* pkB = peaks + (((size_t)b * K_ + SKEL_B[c]) * P_ + j) * 3;

    cudaGridDependencySynchronize();   // PDL: wait for select grid + mem flush

    if (gid >= NCELLS) return;

    float axi = __ldg(pkA + 0), ayi = __ldg(pkA + 1), sa = __ldg(pkA + 2);
    float bxj = __ldg(pkB + 0), byj = __ldg(pkB + 1), sb = __ldg(pkB + 2);

    const float delta = 1.0f / 9.0f;

    float dxl = bxj - axi;
    float dyl = byj - ayi;
    float norm = sqrtf(dxl*dxl + dyl*dyl) + 1e-8f;
    float vx = dxl / norm, vy = dyl / norm;

    int   idx[S_];
    bool  inb[S_];
    #pragma unroll
    for (int s = 0; s < S_; s++) {
        float t2 = (s == S_-1) ? 1.0f : (float)s * delta;
        float xs = axi + dxl * t2;
        float ys = ayi + dyl * t2;
        int xi = __float2int_rz(xs);
        int yi = __float2int_rz(ys);
        inb[s] = (xi >= 0) & (xi < W_) & (yi >= 0) & (yi < H_);
        int xc = min(max(xi, 0), W_ - 1);
        int yc = min(max(yi, 0), H_ - 1);
        idx[s] = yc * W_ + xc;
    }

    float pxv[S_], pyv[S_];
    #pragma unroll
    for (int s = 0; s < S_; s++) pxv[s] = __ldg(pafx + idx[s]);
    #pragma unroll
    for (int s = 0; s < S_; s++) pyv[s] = __ldg(pafy + idx[s]);

    float cnt = 0.0f, sum = 0.0f, cntp = 0.0f;
    #pragma unroll
    for (int s = 0; s < S_; s++) {
        float vs = pxv[s] * vx + pyv[s] * vy;
        if (inb[s]) {
            cnt += 1.0f;
            sum += vs;
            if (vs > PAF_SCORE_THRESH) cntp += 1.0f;
        }
    }

    float denom = fmaxf(cnt, 1.0f);
    float mean  = sum / denom;
    float ratio = cntp / denom;
    bool ok = (cnt > 0.0f) && (mean > 0.0f) && (ratio > PAF_COUNT_THRESH)
              && (sa > PEAK_THRESH) && (sb > PEAK_THRESH);
    conn[gid] = ok ? (mean + 0.5f * (sa + sb)) : 0.0f;
}

// ---------------------------------------------------------------------------
extern "C" void kernel_launch(void* const* d_in, const int* in_sizes, int n_in,
                              void* d_out, int out_size)
{
    const float* heat = (const float*)d_in[0];
    const float* paf  = (const float*)d_in[1];
    if (n_in >= 2 && in_sizes[0] == B_ * 2 * C_ * HW_ && in_sizes[1] == B_ * K_ * HW_) {
        heat = (const float*)d_in[1];
        paf  = (const float*)d_in[0];
    }

    float* out_peaks = (float*)d_out;
    float* out_conn  = out_peaks + (size_t)B_ * K_ * P_ * 3;

    dim3 g1(H_ / CTAROWS, NCH);
    dim3 b1(QX, TY);
    peaks_scan<<<g1, b1>>>(heat);

    // PDL launches: overlap launch/ramp of dependent kernels with producer tail.
    cudaLaunchAttribute attr[1];
    attr[0].id = cudaLaunchAttributeProgrammaticStreamSerialization;
    attr[0].val.programmaticStreamSerializationAllowed = 1;

    {
        cudaLaunchConfig_t cfg = {};
        cfg.gridDim  = dim3(NCH);
        cfg.blockDim = dim3(NT1);
        cfg.attrs = attr;
        cfg.numAttrs = 1;
        if (cudaLaunchKernelEx(&cfg, peaks_select, heat, out_peaks) != cudaSuccess)
            peaks_select<<<NCH, NT1>>>(heat, out_peaks);   // fallback (sync is no-op)
    }
    {
        const int nconn = (NCELLS + NT2 - 1) / NT2;
        cudaLaunchConfig_t cfg = {};
        cfg.gridDim  = dim3(nconn);
        cfg.blockDim = dim3(NT2);
        cfg.attrs = attr;
        cfg.numAttrs = 1;
        if (cudaLaunchKernelEx(&cfg, conn_kernel, paf, out_peaks, out_conn) != cudaSuccess)
            conn_kernel<<<nconn, NT2>>>(paf, out_peaks, out_conn);
    }
}

// round 16
// speedup vs baseline: 3.0450x; 1.0272x over previous
#include <cuda_runtime.h>
#include <cstdint>
#include <cfloat>

#define B_  32
#define K_  17
#define H_  192
#define W_  192
#define C_  19
#define P_  20
#define S_  10
#define HW_ (H_*W_)
#define NCH (B_*K_)

#define PEAK_THRESH      0.1f
#define PAF_SCORE_THRESH 0.05f
#define PAF_COUNT_THRESH 0.8f

#define HOT_T    0.98f       // hot candidate threshold (exact-fallback guarded)
#define CAND_CAP 5120        // full capacity (fallback); hot path uses ~615
#define SURV_CAP 512
#define NBINS    256
#define CTA_BUF  512         // per-CTA hot staging; expected ~205

#define QX   48
#define TY   8
#define RPT  8
#define CTAROWS (TY*RPT)
#define NTS  (QX*TY)

__constant__ int SKEL_A[C_] = {15,13,16,14,11, 5, 6, 5, 5, 6, 7, 8, 1, 0, 0, 1, 2, 3, 4};
__constant__ int SKEL_B[C_] = {13,11,14,12,12,11,12, 6, 7, 8, 9,10, 2, 1, 2, 3, 4, 5, 6};

__device__ unsigned long long g_keys[NCH][CAND_CAP];
__device__ int g_count[NCH];
__device__ int g_hist[NCH][NBINS];

__device__ __forceinline__ float fmax3(float a, float b, float c) {
    return fmaxf(a, fmaxf(b, c));
}

// ---------------------------------------------------------------------------
// Kernel 1a: streaming peak scan with HOT threshold (stores peaks >= 0.98).
// ---------------------------------------------------------------------------
__global__ __launch_bounds__(NTS)
void peaks_scan(const float* __restrict__ heat)
{
    const int bk = blockIdx.y;
    const float* __restrict__ h = heat + (size_t)bk * HW_;

    const int qx  = threadIdx.x;
    const int y0  = blockIdx.x * CTAROWS + threadIdx.y * RPT;
    const int tid = threadIdx.y * QX + threadIdx.x;
    const int lane = tid & 31;
    const int x0  = qx * 4;

    __shared__ unsigned long long s_buf[CTA_BUF];
    __shared__ int s_hist[NBINS];
    __shared__ int s_cnt;
    __shared__ int s_gbase;

    for (int i = tid; i < NBINS; i += NTS) s_hist[i] = 0;
    if (tid == 0) s_cnt = 0;
    __syncthreads();

    const bool is_l = (lane == 0)  && (qx > 0);
    const bool is_r = (lane == 31) && (qx < QX - 1);
    const float4 NEG4 = make_float4(-FLT_MAX, -FLT_MAX, -FLT_MAX, -FLT_MAX);
    const float THR = HOT_T;

    float4 a, b;
    float el_a = -FLT_MAX, el_b = -FLT_MAX;
    float er_a = -FLT_MAX, er_b = -FLT_MAX;
    {
        const float* rw = h + (size_t)y0 * W_;
        b = __ldg((const float4*)rw + qx);
        if (is_l) el_b = __ldg(rw + x0 - 1);
        if (is_r) er_b = __ldg(rw + x0 + 4);
        if (y0 > 0) {
            a = __ldg((const float4*)(rw - W_) + qx);
            if (is_l) el_a = __ldg(rw - W_ + x0 - 1);
            if (is_r) er_a = __ldg(rw - W_ + x0 + 4);
        } else {
            a = NEG4;
        }
    }

    #pragma unroll
    for (int r = 0; r < RPT; r++) {
        const int y = y0 + r;
        float4 c;
        float el_c = -FLT_MAX, er_c = -FLT_MAX;
        if (y + 1 < H_) {
            const float* rd = h + (size_t)(y + 1) * W_;
            c = __ldg((const float4*)rd + qx);
            if (is_l) el_c = __ldg(rd + x0 - 1);
            if (is_r) er_c = __ldg(rd + x0 + 4);
        } else {
            c = NEG4;
        }

        float v0 = fmax3(a.x, b.x, c.x);
        float v1 = fmax3(a.y, b.y, c.y);
        float v2 = fmax3(a.z, b.z, c.z);
        float v3 = fmax3(a.w, b.w, c.w);

        float vl = __shfl_up_sync(0xffffffffu, v3, 1);
        if (lane == 0)   vl = fmax3(el_a, el_b, el_c);
        if (qx == 0)     vl = -FLT_MAX;
        float vr = __shfl_down_sync(0xffffffffu, v0, 1);
        if (lane == 31)  vr = fmax3(er_a, er_b, er_c);
        if (qx == QX-1)  vr = -FLT_MAX;

        float m01 = fmaxf(v0, v1);
        float m23 = fmaxf(v2, v3);
        float w0 = fmaxf(fmaxf(vl,  m01), THR);
        float w1 = fmaxf(fmaxf(m01, v2),  THR);
        float w2 = fmaxf(fmaxf(v1,  m23), THR);
        float w3 = fmaxf(fmaxf(m23, vr),  THR);

        const bool p0 = (b.x >= w0);
        const bool p1 = (b.y >= w1);
        const bool p2 = (b.z >= w2);
        const bool p3 = (b.w >= w3);

        unsigned m0 = __ballot_sync(0xffffffffu, p0);
        unsigned m1 = __ballot_sync(0xffffffffu, p1);
        unsigned m2 = __ballot_sync(0xffffffffu, p2);
        unsigned m3 = __ballot_sync(0xffffffffu, p3);
        int n0 = __popc(m0), n1 = __popc(m1), n2 = __popc(m2);
        int total = n0 + n1 + n2 + __popc(m3);

        if (total) {
            int base = 0;
            if (lane == 0) base = atomicAdd(&s_cnt, total);
            base = __shfl_sync(0xffffffffu, base, 0);
            const unsigned lt = (1u << lane) - 1u;
            const int prow = y * W_ + x0;
            #define STORE_PK(v, pos, pix)                                           \
                do { int _p = (pos);                                                \
                     if (_p < CTA_BUF) {                                            \
                         s_buf[_p] = ((unsigned long long)__float_as_uint(v) << 32) \
                                   | (unsigned)(0xFFFFFFFFu - (unsigned)(pix));     \
                         atomicAdd(&s_hist[min(NBINS-1, (int)((v)*(float)NBINS))], 1);\
                     } } while (0)
            if (p0) STORE_PK(b.x, base + __popc(m0 & lt),                prow);
            if (p1) STORE_PK(b.y, base + n0 + __popc(m1 & lt),           prow + 1);
            if (p2) STORE_PK(b.z, base + n0 + n1 + __popc(m2 & lt),      prow + 2);
            if (p3) STORE_PK(b.w, base + n0 + n1 + n2 + __popc(m3 & lt), prow + 3);
            #undef STORE_PK
        }

        a = b; b = c;
        el_a = el_b; el_b = el_c;
        er_a = er_b; er_b = er_c;
    }
    __syncthreads();

    const int n = min(s_cnt, CTA_BUF);
    if (tid == 0 && n > 0) s_gbase = atomicAdd(&g_count[bk], n);
    __syncthreads();

    if (n > 0) {
        const int gbase = s_gbase;
        for (int i = tid; i < n; i += NTS) {
            int pos = gbase + i;
            if (pos < CAND_CAP) g_keys[bk][pos] = s_buf[i];
        }
    }
    for (int i = tid; i < NBINS; i += NTS) {
        int hv = s_hist[i];
        if (hv) atomicAdd(&g_hist[bk][i], hv);
    }
}

// ---------------------------------------------------------------------------
// Kernel 1b: per-channel top-20 selection with exact fallback + PDL sync.
// ---------------------------------------------------------------------------
#define NT1 256
__global__ __launch_bounds__(NT1)
void peaks_select(const float* __restrict__ heat, float* __restrict__ out_peaks)
{
    cudaGridDependencySynchronize();   // PDL: wait for scan grid

    const int bk = blockIdx.x;
    const float* __restrict__ h = heat + (size_t)bk * HW_;

    __shared__ unsigned long long surv[SURV_CAP];
    __shared__ int   s_hist[NBINS];
    __shared__ int   s_nc, s_nsurv, s_tbin, s_cnt;
    __shared__ unsigned long long sel_key[P_];

    const int tid  = threadIdx.x;
    const int lane = tid & 31;
    const int wid  = tid >> 5;

    // stage hot count + histogram; reset scratch
    if (tid == 0) {
        s_nc = min(g_count[bk], CAND_CAP);
        g_count[bk] = 0;
        s_nsurv = 0;
    }
    s_hist[tid] = g_hist[bk][tid];
    g_hist[bk][tid] = 0;
    __syncthreads();
    int nc = s_nc;

    // ---------- exact fallback: fewer than P_ hot peaks -> full rescan ----------
    if (nc < P_) {
        s_hist[tid] = 0;
        if (tid == 0) s_cnt = 0;
        __syncthreads();
        for (int p = tid; p < HW_; p += NT1) {
            float v = h[p];
            if (v <= PEAK_THRESH) continue;
            int y = p / W_;
            int x = p - y * W_;
            bool pk = true;
            if (x > 0        && v < h[p - 1])  pk = false;
            if (pk && x < W_-1 && v < h[p + 1])  pk = false;
            if (pk && y > 0) {
                const float* r = h + p - W_;
                if (v < r[0]) pk = false;
                if (pk && x > 0      && v < r[-1]) pk = false;
                if (pk && x < W_-1   && v < r[ 1]) pk = false;
            }
            if (pk && y < H_-1) {
                const float* r = h + p + W_;
                if (v < r[0]) pk = false;
                if (pk && x > 0      && v < r[-1]) pk = false;
                if (pk && x < W_-1   && v < r[ 1]) pk = false;
            }
            if (pk) {
                int pos = atomicAdd(&s_cnt, 1);
                if (pos < CAND_CAP) {
                    g_keys[bk][pos] =
                        ((unsigned long long)__float_as_uint(v) << 32)
                        | (unsigned)(0xFFFFFFFFu - (unsigned)p);
                    atomicAdd(&s_hist[min(NBINS-1, (int)(v * (float)NBINS))], 1);
                }
            }
        }
        __syncthreads();
        nc = min(s_cnt, CAND_CAP);
    }

    // ---------- threshold search (warp 0) ----------
    if (wid == 0) {
        const int need = min(P_, nc);
        int lsum = 0;
        int lh[8];
        #pragma unroll
        for (int k = 0; k < 8; k++) {
            lh[k] = s_hist[NBINS - 1 - (lane * 8 + k)];
            lsum += lh[k];
        }
        int excl = lsum;
        #pragma unroll
        for (int d = 1; d < 32; d <<= 1) {
            int nn = __shfl_up_sync(0xffffffffu, excl, d);
            if (lane >= d) excl += nn;
        }
        int tot = __shfl_sync(0xffffffffu, excl, 31);
        excl -= lsum;

        int tb = 0;
        if (need > 0 && tot >= need) {
            bool crossing = (excl < need) && (excl + lsum >= need);
            unsigned cm = __ballot_sync(0xffffffffu, crossing);
            int src = __ffs(cm) - 1;
            if (lane == src) {
                int cum = excl;
                #pragma unroll
                for (int k = 0; k < 8; k++) {
                    cum += lh[k];
                    if (cum >= need) { tb = NBINS - 1 - (lane * 8 + k); break; }
                }
            }
            tb = __shfl_sync(0xffffffffu, tb, src);
        }
        if (lane == 0) s_tbin = tb;
    }
    __syncthreads();
    const int tbin = s_tbin;

    // ---------- filter survivors ----------
    for (int i = tid; i < nc; i += NT1) {
        unsigned long long k = g_keys[bk][i];
        float sc = __uint_as_float((unsigned)(k >> 32));
        int bin = min(NBINS - 1, (int)(sc * (float)NBINS));
        if (bin >= tbin) {
            int slot = atomicAdd(&s_nsurv, 1);
            if (slot < SURV_CAP) surv[slot] = k;
        }
    }
    __syncthreads();

    // ---------- warp-0 exact top-20 ----------
    if (wid == 0) {
        unsigned long long* list;
        int len;
        if (s_nsurv <= SURV_CAP) { list = surv; len = s_nsurv; }
        else                     { list = &g_keys[bk][0]; len = nc; }

        for (int r = 0; r < P_; r++) {
            unsigned long long bkey = 0ull;
            int bidx = -1;
            for (int i = lane; i < len; i += 32) {
                unsigned long long k = list[i];
                if (k > bkey) { bkey = k; bidx = i; }
            }
            #pragma unroll
            for (int o = 16; o > 0; o >>= 1) {
                unsigned long long ok = __shfl_down_sync(0xffffffffu, bkey, o);
                int oi = __shfl_down_sync(0xffffffffu, bidx, o);
                if (ok > bkey) { bkey = ok; bidx = oi; }
            }
            if (lane == 0) {
                sel_key[r] = bkey;
                if (bidx >= 0) list[bidx] = 0ull;
            }
            __syncwarp();
        }
    }
    __syncthreads();

    // ---------- subpixel refine + write ----------
    if (tid < P_) {
        unsigned long long k = sel_key[tid];
        float px = 0.0f, py = 0.0f, so = 0.0f;
        if (k != 0ull) {
            float sc = __uint_as_float((unsigned)(k >> 32));
            int p = (int)(0xFFFFFFFFu - (unsigned)(k & 0xFFFFFFFFull));
            int y = p / W_;
            int x = p - y * W_;
            float ddx = 0.0f, ddy = 0.0f;
            if (x > 0 && x < W_-1 && y > 0 && y < H_-1) {
                float c  = h[p];
                float rr = h[p + 1],  ll = h[p - 1];
                float dd = h[p + W_], uu = h[p - W_];
                float dx  = 0.5f * (rr - ll);
                float dxx = (rr + ll) - 2.0f * c;
                if (dxx != 0.0f) dx = dx / (-dxx);
                float dy  = 0.5f * (dd - uu);
                float dyy = (dd + uu) - 2.0f * c;
                if (dyy != 0.0f) dy = dy / (-dyy);
                ddx = dx; ddy = dy;
            }
            px = (float)x + ddx;
            py = (float)y + ddy;
            so = sc;
        }
        float* o = out_peaks + ((size_t)bk * P_ + tid) * 3;
        o[0] = px; o[1] = py; o[2] = so;
    }
}

// ---------------------------------------------------------------------------
// Kernel 2: flat one-thread-per-cell PAF line-integral scoring + PDL sync.
// ---------------------------------------------------------------------------
#define NT2 256
#define NCELLS (B_*C_*P_*P_)
__global__ __launch_bounds__(NT2)
void conn_kernel(const float* __restrict__ paf,
                 const float* __restrict__ peaks,
                 float* __restrict__ conn)
{
    const int gid = blockIdx.x * NT2 + threadIdx.x;

    int j = gid % P_;
    int t = gid / P_;
    int i = t % P_;  t /= P_;
    int c = t % C_;
    int b = t / C_;

    const float* __restrict__ pafx = paf + ((size_t)b * (2*C_) + 2*c) * HW_;
    const float* __restrict__ pafy = pafx + HW_;
    const float* pkA = peaks + (((size_t)b * K_ + SKEL_A[c]) * P_ + i) * 3;
    const float* pkB = peaks + (((size_t)b * K_ + SKEL_B[c]) * P_ + j) * 3;

    cudaGridDependencySynchronize();   // PDL: wait for select grid

    if (gid >= NCELLS) return;

    float axi = __ldg(pkA + 0), ayi = __ldg(pkA + 1), sa = __ldg(pkA + 2);
    float bxj = __ldg(pkB + 0), byj = __ldg(pkB + 1), sb = __ldg(pkB + 2);

    const float delta = 1.0f / 9.0f;

    float dxl = bxj - axi;
    float dyl = byj - ayi;
    float norm = sqrtf(dxl*dxl + dyl*dyl) + 1e-8f;
    float vx = dxl / norm, vy = dyl / norm;

    int   idx[S_];
    bool  inb[S_];
    #pragma unroll
    for (int s = 0; s < S_; s++) {
        float t2 = (s == S_-1) ? 1.0f : (float)s * delta;
        float xs = axi + dxl * t2;
        float ys = ayi + dyl * t2;
        int xi = __float2int_rz(xs);
        int yi = __float2int_rz(ys);
        inb[s] = (xi >= 0) & (xi < W_) & (yi >= 0) & (yi < H_);
        int xc = min(max(xi, 0), W_ - 1);
        int yc = min(max(yi, 0), H_ - 1);
        idx[s] = yc * W_ + xc;
    }

    float pxv[S_], pyv[S_];
    #pragma unroll
    for (int s = 0; s < S_; s++) pxv[s] = __ldg(pafx + idx[s]);
    #pragma unroll
    for (int s = 0; s < S_; s++) pyv[s] = __ldg(pafy + idx[s]);

    float cnt = 0.0f, sum = 0.0f, cntp = 0.0f;
    #pragma unroll
    for (int s = 0; s < S_; s++) {
        float vs = pxv[s] * vx + pyv[s] * vy;
        if (inb[s]) {
            cnt += 1.0f;
            sum += vs;
            if (vs > PAF_SCORE_THRESH) cntp += 1.0f;
        }
    }

    float denom = fmaxf(cnt, 1.0f);
    float mean  = sum / denom;
    float ratio = cntp / denom;
    bool ok = (cnt > 0.0f) && (mean > 0.0f) && (ratio > PAF_COUNT_THRESH)
              && (sa > PEAK_THRESH) && (sb > PEAK_THRESH);
    conn[gid] = ok ? (mean + 0.5f * (sa + sb)) : 0.0f;
}

// ---------------------------------------------------------------------------
extern "C" void kernel_launch(void* const* d_in, const int* in_sizes, int n_in,
                              void* d_out, int out_size)
{
    const float* heat = (const float*)d_in[0];
    const float* paf  = (const float*)d_in[1];
    if (n_in >= 2 && in_sizes[0] == B_ * 2 * C_ * HW_ && in_sizes[1] == B_ * K_ * HW_) {
        heat = (const float*)d_in[1];
        paf  = (const float*)d_in[0];
    }

    float* out_peaks = (float*)d_out;
    float* out_conn  = out_peaks + (size_t)B_ * K_ * P_ * 3;

    dim3 g1(H_ / CTAROWS, NCH);
    dim3 b1(QX, TY);
    peaks_scan<<<g1, b1>>>(heat);

    cudaLaunchAttribute attr[1];
    attr[0].id = cudaLaunchAttributeProgrammaticStreamSerialization;
    attr[0].val.programmaticStreamSerializationAllowed = 1;

    {
        cudaLaunchConfig_t cfg = {};
        cfg.gridDim  = dim3(NCH);
        cfg.blockDim = dim3(NT1);
        cfg.attrs = attr;
        cfg.numAttrs = 1;
        if (cudaLaunchKernelEx(&cfg, peaks_select, heat, out_peaks) != cudaSuccess)
            peaks_select<<<NCH, NT1>>>(heat, out_peaks);
    }
    {
        const int nconn = (NCELLS + NT2 - 1) / NT2;
        cudaLaunchConfig_t cfg = {};
        cfg.gridDim  = dim3(nconn);
        cfg.blockDim = dim3(NT2);
        cfg.attrs = attr;
        cfg.numAttrs = 1;
        if (cudaLaunchKernelEx(&cfg, conn_kernel, paf, out_peaks, out_conn) != cudaSuccess)
            conn_kernel<<<nconn, NT2>>>(paf, out_peaks, out_conn);
    }
}

// round 17
// speedup vs baseline: 3.4120x; 1.1205x over previous
#include <cuda_runtime.h>
#include <cstdint>
#include <cfloat>

#define B_  32
#define K_  17
#define H_  192
#define W_  192
#define C_  19
#define P_  20
#define S_  10
#define HW_ (H_*W_)
#define NCH (B_*K_)

#define PEAK_THRESH      0.1f
#define PAF_SCORE_THRESH 0.05f
#define PAF_COUNT_THRESH 0.8f

#define HOT_T    0.998f      // hot candidate threshold (exact-fallback guarded)
#define CAND_CAP 5120        // full capacity (fallback path)
#define SURV_CAP 512
#define NBINS    256
#define CTA_BUF  256         // per-CTA hot staging; expected ~24

#define QX   48
#define TY   8
#define RPT  8
#define CTAROWS (TY*RPT)
#define NTS  (QX*TY)

__constant__ int SKEL_A[C_] = {15,13,16,14,11, 5, 6, 5, 5, 6, 7, 8, 1, 0, 0, 1, 2, 3, 4};
__constant__ int SKEL_B[C_] = {13,11,14,12,12,11,12, 6, 7, 8, 9,10, 2, 1, 2, 3, 4, 5, 6};

__device__ unsigned long long g_keys[NCH][CAND_CAP];
__device__ int g_count[NCH];
__device__ int g_hist[NCH][NBINS];

__device__ __forceinline__ float fmax3(float a, float b, float c) {
    return fmaxf(a, fmaxf(b, c));
}

// ---------------------------------------------------------------------------
// Kernel 1a: streaming peak scan, HOT threshold + warp-uniform row early-out.
// ---------------------------------------------------------------------------
__global__ __launch_bounds__(NTS)
void peaks_scan(const float* __restrict__ heat)
{
    const int bk = blockIdx.y;
    const float* __restrict__ h = heat + (size_t)bk * HW_;

    const int qx  = threadIdx.x;
    const int y0  = blockIdx.x * CTAROWS + threadIdx.y * RPT;
    const int tid = threadIdx.y * QX + threadIdx.x;
    const int lane = tid & 31;
    const int x0  = qx * 4;

    __shared__ unsigned long long s_buf[CTA_BUF];
    __shared__ int s_hist[NBINS];
    __shared__ int s_cnt;
    __shared__ int s_gbase;

    for (int i = tid; i < NBINS; i += NTS) s_hist[i] = 0;
    if (tid == 0) s_cnt = 0;
    __syncthreads();

    const bool is_l = (lane == 0)  && (qx > 0);
    const bool is_r = (lane == 31) && (qx < QX - 1);
    const float4 NEG4 = make_float4(-FLT_MAX, -FLT_MAX, -FLT_MAX, -FLT_MAX);
    const float THR = HOT_T;

    float4 a, b;
    float el_a = -FLT_MAX, el_b = -FLT_MAX;
    float er_a = -FLT_MAX, er_b = -FLT_MAX;
    {
        const float* rw = h + (size_t)y0 * W_;
        b = __ldg((const float4*)rw + qx);
        if (is_l) el_b = __ldg(rw + x0 - 1);
        if (is_r) er_b = __ldg(rw + x0 + 4);
        if (y0 > 0) {
            a = __ldg((const float4*)(rw - W_) + qx);
            if (is_l) el_a = __ldg(rw - W_ + x0 - 1);
            if (is_r) er_a = __ldg(rw - W_ + x0 + 4);
        } else {
            a = NEG4;
        }
    }

    #pragma unroll
    for (int r = 0; r < RPT; r++) {
        const int y = y0 + r;
        float4 c;
        float el_c = -FLT_MAX, er_c = -FLT_MAX;
        if (y + 1 < H_) {
            const float* rd = h + (size_t)(y + 1) * W_;
            c = __ldg((const float4*)rd + qx);
            if (is_l) el_c = __ldg(rd + x0 - 1);
            if (is_r) er_c = __ldg(rd + x0 + 4);
        } else {
            c = NEG4;
        }

        // warp-uniform early-out: any center value that could be a hot peak?
        const bool q = fmaxf(fmaxf(b.x, b.y), fmaxf(b.z, b.w)) >= THR;
        if (__ballot_sync(0xffffffffu, q) != 0u) {
            float v0 = fmax3(a.x, b.x, c.x);
            float v1 = fmax3(a.y, b.y, c.y);
            float v2 = fmax3(a.z, b.z, c.z);
            float v3 = fmax3(a.w, b.w, c.w);

            float vl = __shfl_up_sync(0xffffffffu, v3, 1);
            if (lane == 0)   vl = fmax3(el_a, el_b, el_c);
            if (qx == 0)     vl = -FLT_MAX;
            float vr = __shfl_down_sync(0xffffffffu, v0, 1);
            if (lane == 31)  vr = fmax3(er_a, er_b, er_c);
            if (qx == QX-1)  vr = -FLT_MAX;

            float m01 = fmaxf(v0, v1);
            float m23 = fmaxf(v2, v3);
            float w0 = fmaxf(fmaxf(vl,  m01), THR);
            float w1 = fmaxf(fmaxf(m01, v2),  THR);
            float w2 = fmaxf(fmaxf(v1,  m23), THR);
            float w3 = fmaxf(fmaxf(m23, vr),  THR);

            const bool p0 = (b.x >= w0);
            const bool p1 = (b.y >= w1);
            const bool p2 = (b.z >= w2);
            const bool p3 = (b.w >= w3);

            unsigned m0 = __ballot_sync(0xffffffffu, p0);
            unsigned m1 = __ballot_sync(0xffffffffu, p1);
            unsigned m2 = __ballot_sync(0xffffffffu, p2);
            unsigned m3 = __ballot_sync(0xffffffffu, p3);
            int n0 = __popc(m0), n1 = __popc(m1), n2 = __popc(m2);
            int total = n0 + n1 + n2 + __popc(m3);

            if (total) {
                int base = 0;
                if (lane == 0) base = atomicAdd(&s_cnt, total);
                base = __shfl_sync(0xffffffffu, base, 0);
                const unsigned lt = (1u << lane) - 1u;
                const int prow = y * W_ + x0;
                #define STORE_PK(v, pos, pix)                                           \
                    do { int _p = (pos);                                                \
                         if (_p < CTA_BUF) {                                            \
                             s_buf[_p] = ((unsigned long long)__float_as_uint(v) << 32) \
                                       | (unsigned)(0xFFFFFFFFu - (unsigned)(pix));     \
                             atomicAdd(&s_hist[min(NBINS-1, (int)((v)*(float)NBINS))], 1);\
                         } } while (0)
                if (p0) STORE_PK(b.x, base + __popc(m0 & lt),                prow);
                if (p1) STORE_PK(b.y, base + n0 + __popc(m1 & lt),           prow + 1);
                if (p2) STORE_PK(b.z, base + n0 + n1 + __popc(m2 & lt),      prow + 2);
                if (p3) STORE_PK(b.w, base + n0 + n1 + n2 + __popc(m3 & lt), prow + 3);
                #undef STORE_PK
            }
        }

        a = b; b = c;
        el_a = el_b; el_b = el_c;
        er_a = er_b; er_b = er_c;
    }
    __syncthreads();

    const int n = min(s_cnt, CTA_BUF);
    if (tid == 0 && n > 0) s_gbase = atomicAdd(&g_count[bk], n);
    __syncthreads();

    if (n > 0) {
        const int gbase = s_gbase;
        for (int i = tid; i < n; i += NTS) {
            int pos = gbase + i;
            if (pos < CAND_CAP) g_keys[bk][pos] = s_buf[i];
        }
    }
    for (int i = tid; i < NBINS; i += NTS) {
        int hv = s_hist[i];
        if (hv) atomicAdd(&g_hist[bk][i], hv);
    }
}

// ---------------------------------------------------------------------------
// Kernel 1b: per-channel top-20 selection with exact fallback + PDL sync.
// ---------------------------------------------------------------------------
#define NT1 256
__global__ __launch_bounds__(NT1)
void peaks_select(const float* __restrict__ heat, float* __restrict__ out_peaks)
{
    cudaGridDependencySynchronize();   // PDL: wait for scan grid

    const int bk = blockIdx.x;
    const float* __restrict__ h = heat + (size_t)bk * HW_;

    __shared__ unsigned long long surv[SURV_CAP];
    __shared__ int   s_hist[NBINS];
    __shared__ int   s_nc, s_nsurv, s_tbin, s_cnt;
    __shared__ unsigned long long sel_key[P_];

    const int tid  = threadIdx.x;
    const int lane = tid & 31;
    const int wid  = tid >> 5;

    if (tid == 0) {
        s_nc = min(g_count[bk], CAND_CAP);
        g_count[bk] = 0;
        s_nsurv = 0;
    }
    s_hist[tid] = g_hist[bk][tid];
    g_hist[bk][tid] = 0;
    __syncthreads();
    int nc = s_nc;

    // ---------- exact fallback: fewer than P_ hot peaks -> full rescan ----------
    if (nc < P_) {
        s_hist[tid] = 0;
        if (tid == 0) s_cnt = 0;
        __syncthreads();
        for (int p = tid; p < HW_; p += NT1) {
            float v = h[p];
            if (v <= PEAK_THRESH) continue;
            int y = p / W_;
            int x = p - y * W_;
            bool pk = true;
            if (x > 0        && v < h[p - 1])  pk = false;
            if (pk && x < W_-1 && v < h[p + 1])  pk = false;
            if (pk && y > 0) {
                const float* r = h + p - W_;
                if (v < r[0]) pk = false;
                if (pk && x > 0      && v < r[-1]) pk = false;
                if (pk && x < W_-1   && v < r[ 1]) pk = false;
            }
            if (pk && y < H_-1) {
                const float* r = h + p + W_;
                if (v < r[0]) pk = false;
                if (pk && x > 0      && v < r[-1]) pk = false;
                if (pk && x < W_-1   && v < r[ 1]) pk = false;
            }
            if (pk) {
                int pos = atomicAdd(&s_cnt, 1);
                if (pos < CAND_CAP) {
                    g_keys[bk][pos] =
                        ((unsigned long long)__float_as_uint(v) << 32)
                        | (unsigned)(0xFFFFFFFFu - (unsigned)p);
                    atomicAdd(&s_hist[min(NBINS-1, (int)(v * (float)NBINS))], 1);
                }
            }
        }
        __syncthreads();
        nc = min(s_cnt, CAND_CAP);
    }

    // ---------- threshold search (warp 0) ----------
    if (wid == 0) {
        const int need = min(P_, nc);
        int lsum = 0;
        int lh[8];
        #pragma unroll
        for (int k = 0; k < 8; k++) {
            lh[k] = s_hist[NBINS - 1 - (lane * 8 + k)];
            lsum += lh[k];
        }
        int excl = lsum;
        #pragma unroll
        for (int d = 1; d < 32; d <<= 1) {
            int nn = __shfl_up_sync(0xffffffffu, excl, d);
            if (lane >= d) excl += nn;
        }
        int tot = __shfl_sync(0xffffffffu, excl, 31);
        excl -= lsum;

        int tb = 0;
        if (need > 0 && tot >= need) {
            bool crossing = (excl < need) && (excl + lsum >= need);
            unsigned cm = __ballot_sync(0xffffffffu, crossing);
            int src = __ffs(cm) - 1;
            if (lane == src) {
                int cum = excl;
                #pragma unroll
                for (int k = 0; k < 8; k++) {
                    cum += lh[k];
                    if (cum >= need) { tb = NBINS - 1 - (lane * 8 + k); break; }
                }
            }
            tb = __shfl_sync(0xffffffffu, tb, src);
        }
        if (lane == 0) s_tbin = tb;
    }
    __syncthreads();
    const int tbin = s_tbin;

    // ---------- filter survivors ----------
    for (int i = tid; i < nc; i += NT1) {
        unsigned long long k = g_keys[bk][i];
        float sc = __uint_as_float((unsigned)(k >> 32));
        int bin = min(NBINS - 1, (int)(sc * (float)NBINS));
        if (bin >= tbin) {
            int slot = atomicAdd(&s_nsurv, 1);
            if (slot < SURV_CAP) surv[slot] = k;
        }
    }
    __syncthreads();

    // ---------- warp-0 exact top-20 ----------
    if (wid == 0) {
        unsigned long long* list;
        int len;
        if (s_nsurv <= SURV_CAP) { list = surv; len = s_nsurv; }
        else                     { list = &g_keys[bk][0]; len = nc; }

        for (int r = 0; r < P_; r++) {
            unsigned long long bkey = 0ull;
            int bidx = -1;
            for (int i = lane; i < len; i += 32) {
                unsigned long long k = list[i];
                if (k > bkey) { bkey = k; bidx = i; }
            }
            #pragma unroll
            for (int o = 16; o > 0; o >>= 1) {
                unsigned long long ok = __shfl_down_sync(0xffffffffu, bkey, o);
                int oi = __shfl_down_sync(0xffffffffu, bidx, o);
                if (ok > bkey) { bkey = ok; bidx = oi; }
            }
            if (lane == 0) {
                sel_key[r] = bkey;
                if (bidx >= 0) list[bidx] = 0ull;
            }
            __syncwarp();
        }
    }
    __syncthreads();

    // ---------- subpixel refine + write ----------
    if (tid < P_) {
        unsigned long long k = sel_key[tid];
        float px = 0.0f, py = 0.0f, so = 0.0f;
        if (k != 0ull) {
            float sc = __uint_as_float((unsigned)(k >> 32));
            int p = (int)(0xFFFFFFFFu - (unsigned)(k & 0xFFFFFFFFull));
            int y = p / W_;
            int x = p - y * W_;
            float ddx = 0.0f, ddy = 0.0f;
            if (x > 0 && x < W_-1 && y > 0 && y < H_-1) {
                float c  = h[p];
                float rr = h[p + 1],  ll = h[p - 1];
                float dd = h[p + W_], uu = h[p - W_];
                float dx  = 0.5f * (rr - ll);
                float dxx = (rr + ll) - 2.0f * c;
                if (dxx != 0.0f) dx = dx / (-dxx);
                float dy  = 0.5f * (dd - uu);
                float dyy = (dd + uu) - 2.0f * c;
                if (dyy != 0.0f) dy = dy / (-dyy);
                ddx = dx; ddy = dy;
            }
            px = (float)x + ddx;
            py = (float)y + ddy;
            so = sc;
        }
        float* o = out_peaks + ((size_t)bk * P_ + tid) * 3;
        o[0] = px; o[1] = py; o[2] = so;
    }
}

// ---------------------------------------------------------------------------
// Kernel 2: flat one-thread-per-cell PAF line-integral scoring + PDL sync.
// ---------------------------------------------------------------------------
#define NT2 256
#define NCELLS (B_*C_*P_*P_)
__global__ __launch_bounds__(NT2)
void conn_kernel(const float* __restrict__ paf,
                 const float* __restrict__ peaks,
                 float* __restrict__ conn)
{
    const int gid = blockIdx.x * NT2 + threadIdx.x;

    int j = gid % P_;
    int t = gid / P_;
    int i = t % P_;  t /= P_;
    int c = t % C_;
    int b = t / C_;

    const float* __restrict__ pafx = paf + ((size_t)b * (2*C_) + 2*c) * HW_;
    const float* __restrict__ pafy = pafx + HW_;
    const float* pkA = peaks + (((size_t)b * K_ + SKEL_A[c]) * P_ + i) * 3;
    const float* pkB = peaks + (((size_t)b * K_ + SKEL_B[c]) * P_ + j) * 3;

    cudaGridDependencySynchronize();   // PDL: wait for select grid

    if (gid >= NCELLS) return;

    float axi = __ldg(pkA + 0), ayi = __ldg(pkA + 1), sa = __ldg(pkA + 2);
    float bxj = __ldg(pkB + 0), byj = __ldg(pkB + 1), sb = __ldg(pkB + 2);

    const float delta = 1.0f / 9.0f;

    float dxl = bxj - axi;
    float dyl = byj - ayi;
    float norm = sqrtf(dxl*dxl + dyl*dyl) + 1e-8f;
    float vx = dxl / norm, vy = dyl / norm;

    int   idx[S_];
    bool  inb[S_];
    #pragma unroll
    for (int s = 0; s < S_; s++) {
        float t2 = (s == S_-1) ? 1.0f : (float)s * delta;
        float xs = axi + dxl * t2;
        float ys = ayi + dyl * t2;
        int xi = __float2int_rz(xs);
        int yi = __float2int_rz(ys);
        inb[s] = (xi >= 0) & (xi < W_) & (yi >= 0) & (yi < H_);
        int xc = min(max(xi, 0), W_ - 1);
        int yc = min(max(yi, 0), H_ - 1);
        idx[s] = yc * W_ + xc;
    }

    float pxv[S_], pyv[S_];
    #pragma unroll
    for (int s = 0; s < S_; s++) pxv[s] = __ldg(pafx + idx[s]);
    #pragma unroll
    for (int s = 0; s < S_; s++) pyv[s] = __ldg(pafy + idx[s]);

    float cnt = 0.0f, sum = 0.0f, cntp = 0.0f;
    #pragma unroll
    for (int s = 0; s < S_; s++) {
        float vs = pxv[s] * vx + pyv[s] * vy;
        if (inb[s]) {
            cnt += 1.0f;
            sum += vs;
            if (vs > PAF_SCORE_THRESH) cntp += 1.0f;
        }
    }

    float denom = fmaxf(cnt, 1.0f);
    float mean  = sum / denom;
    float ratio = cntp / denom;
    bool ok = (cnt > 0.0f) && (mean > 0.0f) && (ratio > PAF_COUNT_THRESH)
              && (sa > PEAK_THRESH) && (sb > PEAK_THRESH);
    conn[gid] = ok ? (mean + 0.5f * (sa + sb)) : 0.0f;
}

// ---------------------------------------------------------------------------
extern "C" void kernel_launch(void* const* d_in, const int* in_sizes, int n_in,
                              void* d_out, int out_size)
{
    const float* heat = (const float*)d_in[0];
    const float* paf  = (const float*)d_in[1];
    if (n_in >= 2 && in_sizes[0] == B_ * 2 * C_ * HW_ && in_sizes[1] == B_ * K_ * HW_) {
        heat = (const float*)d_in[1];
        paf  = (const float*)d_in[0];
    }

    float* out_peaks = (float*)d_out;
    float* out_conn  = out_peaks + (size_t)B_ * K_ * P_ * 3;

    dim3 g1(H_ / CTAROWS, NCH);
    dim3 b1(QX, TY);
    peaks_scan<<<g1, b1>>>(heat);

    cudaLaunchAttribute attr[1];
    attr[0].id = cudaLaunchAttributeProgrammaticStreamSerialization;
    attr[0].val.programmaticStreamSerializationAllowed = 1;

    {
        cudaLaunchConfig_t cfg = {};
        cfg.gridDim  = dim3(NCH);
        cfg.blockDim = dim3(NT1);
        cfg.attrs = attr;
        cfg.numAttrs = 1;
        if (cudaLaunchKernelEx(&cfg, peaks_select, heat, out_peaks) != cudaSuccess)
            peaks_select<<<NCH, NT1>>>(heat, out_peaks);
    }
    {
        const int nconn = (NCELLS + NT2 - 1) / NT2;
        cudaLaunchConfig_t cfg = {};
        cfg.gridDim  = dim3(nconn);
        cfg.blockDim = dim3(NT2);
        cfg.attrs = attr;
        cfg.numAttrs = 1;
        if (cudaLaunchKernelEx(&cfg, conn_kernel, paf, out_peaks, out_conn) != cudaSuccess)
            conn_kernel<<<nconn, NT2>>>(paf, out_peaks, out_conn);
    }
}